// round 11
// baseline (speedup 1.0000x reference)
#include <cuda_runtime.h>

// DCTExtractor: gray = 0.299R + 0.587G + 0.114B over (64,3,512,512);
// per 8x8 block: D @ G @ D^T, elementwise * mask; output (64,1,512,512).
//
// Two threads per 8x8 tile (column halves) — R2/R7/R8 structure.
// R9 change: 32-thread (single-warp) CTAs, grid 16384. Finest possible
// work-steal granularity: T_CTA ~2us, straggler tail ~1us. __syncwarp
// replaces __syncthreads. DRAM%% has been flat ~68-72 across occ 22-45%;
// the scheduling tail is the only recoverable time left.

#define H 512
#define W 512
#define CHAN (H * W)
#define N_TILES (64 * 64 * 64)        // 262144
#define N_UNITS (N_TILES * 2)         // 524288 half-tiles
#define THREADS 32

__global__ __launch_bounds__(THREADS)
void dct_extract_kernel(const float* __restrict__ x,
                        const float* __restrict__ dctm,
                        const float* __restrict__ mask,
                        float* __restrict__ out)
{
    __shared__ float sD[64];
    __shared__ float sM[64];
    const int tid = threadIdx.x;
    // 32 threads: each loads two elements of each table.
    sD[tid]      = dctm[tid];
    sD[tid + 32] = dctm[tid + 32];
    sM[tid]      = mask[tid];
    sM[tid + 32] = mask[tid + 32];
    __syncwarp();

    const int gid = blockIdx.x * THREADS + tid;   // 0 .. N_UNITS-1
    const int h   = gid & 1;                      // column half
    const int id  = gid >> 1;                     // tile id
    const int tw  = id & 63;
    const int th  = (id >> 6) & 63;
    const int b   = id >> 12;
    const int hb  = h * 4;

    const float* base = x + (size_t)b * 3 * CHAN
                          + (size_t)(th * 8) * W + (size_t)(tw * 8 + hb);

    // U[i][c] = sum_r D[i][r] * gray[r][c], accumulated while streaming rows.
    float U[8][4];
#pragma unroll
    for (int i = 0; i < 8; i++)
#pragma unroll
        for (int c = 0; c < 4; c++)
            U[i][c] = 0.0f;

#pragma unroll
    for (int r = 0; r < 8; r++) {
        const float* p = base + (size_t)r * W;
        float4 R  = __ldcs((const float4*)(p));
        float4 G  = __ldcs((const float4*)(p + CHAN));
        float4 Bv = __ldcs((const float4*)(p + 2 * CHAN));
        float g0 = 0.299f * R.x + 0.587f * G.x + 0.114f * Bv.x;
        float g1 = 0.299f * R.y + 0.587f * G.y + 0.114f * Bv.y;
        float g2 = 0.299f * R.z + 0.587f * G.z + 0.114f * Bv.z;
        float g3 = 0.299f * R.w + 0.587f * G.w + 0.114f * Bv.w;
#pragma unroll
        for (int i = 0; i < 8; i++) {
            const float d = sD[i * 8 + r];
            U[i][0] = fmaf(d, g0, U[i][0]);
            U[i][1] = fmaf(d, g1, U[i][1]);
            U[i][2] = fmaf(d, g2, U[i][2]);
            U[i][3] = fmaf(d, g3, U[i][3]);
        }
    }

    // Row DCT: out[i][l] = sum_k U_full[i][k] * D[l][k], split over the pair.
    float* o = out + (size_t)b * CHAN
                   + (size_t)(th * 8) * W + (size_t)(tw * 8 + hb);
#pragma unroll
    for (int i = 0; i < 8; i++) {
        float p8[8];
#pragma unroll
        for (int l = 0; l < 8; l++) {
            float acc = 0.0f;
#pragma unroll
            for (int kc = 0; kc < 4; kc++)
                acc = fmaf(U[i][kc], sD[l * 8 + hb + kc], acc);
            p8[l] = acc;
        }
        float res[4];
#pragma unroll
        for (int j = 0; j < 4; j++) {
            // h is uniform per thread; indices into p8 are compile-time.
            float send = h ? p8[j] : p8[4 + j];
            float keep = h ? p8[4 + j] : p8[j];
            float w = __shfl_xor_sync(0xFFFFFFFFu, send, 1);
            res[j] = (keep + w) * sM[i * 8 + hb + j];
        }
        __stcs((float4*)(o + (size_t)i * W),
               make_float4(res[0], res[1], res[2], res[3]));
    }
}

extern "C" void kernel_launch(void* const* d_in, const int* in_sizes, int n_in,
                              void* d_out, int out_size)
{
    const float* x    = (const float*)d_in[0];
    const float* dctm = (const float*)d_in[1];
    const float* mask = (const float*)d_in[2];
    float* out = (float*)d_out;

    dct_extract_kernel<<<N_UNITS / THREADS, THREADS>>>(x, dctm, mask, out);
}

// round 13
// speedup vs baseline: 1.0049x; 1.0049x over previous
#include <cuda_runtime.h>

// DCTExtractor: gray = 0.299R + 0.587G + 0.114B over (64,3,512,512);
// per 8x8 block: D @ G @ D^T, elementwise * mask; output (64,1,512,512).
//
// Two threads per 8x8 tile (column halves); 64-thread CTAs (R8 config,
// best measured 41.09us kernel). R12 change: input loads use DEFAULT cache
// policy (no __ldcs) while stores stay __stcs (evict-first). Measured DRAM
// traffic (233MB) is already below compulsory (268MB) -> cross-replay L2
// hits on x exist; evict-first loads were demoting x and fighting that
// reuse. Stores are dead data and belong evict-first.

#define H 512
#define W 512
#define CHAN (H * W)
#define N_TILES (64 * 64 * 64)        // 262144
#define N_UNITS (N_TILES * 2)         // 524288 half-tiles
#define THREADS 64

__global__ __launch_bounds__(THREADS)
void dct_extract_kernel(const float* __restrict__ x,
                        const float* __restrict__ dctm,
                        const float* __restrict__ mask,
                        float* __restrict__ out)
{
    __shared__ float sD[64];
    __shared__ float sM[64];
    const int tid = threadIdx.x;
    sD[tid] = dctm[tid];
    sM[tid] = mask[tid];
    __syncthreads();

    const int gid = blockIdx.x * THREADS + tid;   // 0 .. N_UNITS-1
    const int h   = gid & 1;                      // column half
    const int id  = gid >> 1;                     // tile id
    const int tw  = id & 63;
    const int th  = (id >> 6) & 63;
    const int b   = id >> 12;
    const int hb  = h * 4;

    const float* base = x + (size_t)b * 3 * CHAN
                          + (size_t)(th * 8) * W + (size_t)(tw * 8 + hb);

    // U[i][c] = sum_r D[i][r] * gray[r][c], accumulated while streaming rows.
    float U[8][4];
#pragma unroll
    for (int i = 0; i < 8; i++)
#pragma unroll
        for (int c = 0; c < 4; c++)
            U[i][c] = 0.0f;

#pragma unroll
    for (int r = 0; r < 8; r++) {
        const float* p = base + (size_t)r * W;
        float4 R  = *(const float4*)(p);
        float4 G  = *(const float4*)(p + CHAN);
        float4 Bv = *(const float4*)(p + 2 * CHAN);
        float g0 = 0.299f * R.x + 0.587f * G.x + 0.114f * Bv.x;
        float g1 = 0.299f * R.y + 0.587f * G.y + 0.114f * Bv.y;
        float g2 = 0.299f * R.z + 0.587f * G.z + 0.114f * Bv.z;
        float g3 = 0.299f * R.w + 0.587f * G.w + 0.114f * Bv.w;
#pragma unroll
        for (int i = 0; i < 8; i++) {
            const float d = sD[i * 8 + r];
            U[i][0] = fmaf(d, g0, U[i][0]);
            U[i][1] = fmaf(d, g1, U[i][1]);
            U[i][2] = fmaf(d, g2, U[i][2]);
            U[i][3] = fmaf(d, g3, U[i][3]);
        }
    }

    // Row DCT: out[i][l] = sum_k U_full[i][k] * D[l][k], split over the pair.
    float* o = out + (size_t)b * CHAN
                   + (size_t)(th * 8) * W + (size_t)(tw * 8 + hb);
#pragma unroll
    for (int i = 0; i < 8; i++) {
        float p8[8];
#pragma unroll
        for (int l = 0; l < 8; l++) {
            float acc = 0.0f;
#pragma unroll
            for (int kc = 0; kc < 4; kc++)
                acc = fmaf(U[i][kc], sD[l * 8 + hb + kc], acc);
            p8[l] = acc;
        }
        float res[4];
#pragma unroll
        for (int j = 0; j < 4; j++) {
            // h is uniform per thread; indices into p8 are compile-time.
            float send = h ? p8[j] : p8[4 + j];
            float keep = h ? p8[4 + j] : p8[j];
            float w = __shfl_xor_sync(0xFFFFFFFFu, send, 1);
            res[j] = (keep + w) * sM[i * 8 + hb + j];
        }
        __stcs((float4*)(o + (size_t)i * W),
               make_float4(res[0], res[1], res[2], res[3]));
    }
}

extern "C" void kernel_launch(void* const* d_in, const int* in_sizes, int n_in,
                              void* d_out, int out_size)
{
    const float* x    = (const float*)d_in[0];
    const float* dctm = (const float*)d_in[1];
    const float* mask = (const float*)d_in[2];
    float* out = (float*)d_out;

    dct_extract_kernel<<<N_UNITS / THREADS, THREADS>>>(x, dctm, mask, out);
}